// round 2
// baseline (speedup 1.0000x reference)
#include <cuda_runtime.h>

#define Nn    50000
#define Ee    800000
#define INDIM 128
#define EMB   32
#define ED    8
#define NL    4
#define NB    64
#define NOUT  10
#define EPS_BN 1e-5f

// ---------------- scratch (device globals; no allocations allowed) ----------
__device__ __align__(16) float g_h[Nn * EMB];
__device__ __align__(16) float g_p[Nn * EMB];
__device__ __align__(16) float g_q[Nn * EMB];
__device__ __align__(16) float g_aggr[Nn * EMB];
__device__ __align__(16) float g_y[(size_t)Ee * EMB];  // 102.4 MB edge scratch
__device__ __align__(16) float g_y3[Nn * EMB];
__device__ __align__(16) float g_y4[Nn * EMB];
__device__ __align__(16) float g_stats[NL * 4 * 2 * EMB];
__device__ __align__(16) float g_pool[NB * EMB];
__device__ __align__(16) float g_cnt[NB];

#define STAT_IDX(l, stage, which, c) ((((l) * 4 + (stage)) * 2 + (which)) * EMB + (c))

// ---------------- small helpers --------------------------------------------
__device__ __forceinline__ float4 f4add(float4 a, float4 b) {
    return make_float4(a.x + b.x, a.y + b.y, a.z + b.z, a.w + b.w);
}
__device__ __forceinline__ void f4fma(float4& a, float s, float4 w) {
    a.x = fmaf(s, w.x, a.x); a.y = fmaf(s, w.y, a.y);
    a.z = fmaf(s, w.z, a.z); a.w = fmaf(s, w.w, a.w);
}

__device__ __forceinline__ void stats_warp_to_shared(float4 sum, float4 ss, int lane,
                                                     int c0, float* s_sum, float* s_ss) {
#pragma unroll
    for (int off = 8; off < 32; off <<= 1) {
        sum.x += __shfl_xor_sync(0xffffffffu, sum.x, off);
        sum.y += __shfl_xor_sync(0xffffffffu, sum.y, off);
        sum.z += __shfl_xor_sync(0xffffffffu, sum.z, off);
        sum.w += __shfl_xor_sync(0xffffffffu, sum.w, off);
        ss.x  += __shfl_xor_sync(0xffffffffu, ss.x, off);
        ss.y  += __shfl_xor_sync(0xffffffffu, ss.y, off);
        ss.z  += __shfl_xor_sync(0xffffffffu, ss.z, off);
        ss.w  += __shfl_xor_sync(0xffffffffu, ss.w, off);
    }
    if (lane < 8) {
        atomicAdd(&s_sum[c0 + 0], sum.x); atomicAdd(&s_sum[c0 + 1], sum.y);
        atomicAdd(&s_sum[c0 + 2], sum.z); atomicAdd(&s_sum[c0 + 3], sum.w);
        atomicAdd(&s_ss[c0 + 0], ss.x);   atomicAdd(&s_ss[c0 + 1], ss.y);
        atomicAdd(&s_ss[c0 + 2], ss.z);   atomicAdd(&s_ss[c0 + 3], ss.w);
    }
}

__device__ __forceinline__ void bn_coeffs(int l, int stage, float inv_n,
                                          const float* __restrict__ gamma,
                                          const float* __restrict__ beta,
                                          int c0, float sc[4], float sh[4]) {
#pragma unroll
    for (int i = 0; i < 4; i++) {
        int c = c0 + i;
        float s1 = g_stats[STAT_IDX(l, stage, 0, c)];
        float s2 = g_stats[STAT_IDX(l, stage, 1, c)];
        float mu = s1 * inv_n;
        float var = s2 * inv_n - mu * mu;
        float rs = rsqrtf(var + EPS_BN);
        sc[i] = rs * gamma[c];
        sh[i] = beta[c] - mu * sc[i];
    }
}

// ---------------- zero kernels ---------------------------------------------
__global__ void k_zero_once() {
    int i = blockIdx.x * blockDim.x + threadIdx.x;
    if (i < NL * 4 * 2 * EMB) g_stats[i] = 0.f;
    if (i < NB * EMB) g_pool[i] = 0.f;
    if (i < NB) g_cnt[i] = 0.f;
}
__global__ void k_zero_aggr() {
    int i = blockIdx.x * blockDim.x + threadIdx.x;
    if (i < Nn * EMB / 4) ((float4*)g_aggr)[i] = make_float4(0.f, 0.f, 0.f, 0.f);
}

// ---------------- lin_in: h = x @ W + b ------------------------------------
__global__ void k_lin_in(const float* __restrict__ x, const float* __restrict__ w,
                         const float* __restrict__ b) {
    __shared__ float ws[INDIM * EMB];
    __shared__ float xs[8][INDIM];
    int tx = threadIdx.x, ty = threadIdx.y;
    int tid = ty * 32 + tx;
    for (int i = tid; i < INDIM * EMB; i += 256) ws[i] = w[i];
    int base = blockIdx.x * 8;
    for (int i = tid; i < 8 * INDIM; i += 256) {
        int nloc = i >> 7, k = i & 127;
        xs[nloc][k] = x[(base + nloc) * INDIM + k];
    }
    __syncthreads();
    float acc = b[tx];
#pragma unroll 8
    for (int k = 0; k < INDIM; k++) acc = fmaf(xs[ty][k], ws[k * EMB + tx], acc);
    g_h[(base + ty) * EMB + tx] = acc;
}

// ---------------- per-layer node projections p, q (b1 folded into p) -------
__global__ void k_pq(const float* __restrict__ w1, const float* __restrict__ b1) {
    __shared__ float wd[EMB * EMB];
    __shared__ float wsr[EMB * EMB];
    __shared__ float hs[8][EMB];
    int tx = threadIdx.x, ty = threadIdx.y;
    int tid = ty * 32 + tx;
    for (int i = tid; i < EMB * EMB; i += 256) { wd[i] = w1[i]; wsr[i] = w1[EMB * EMB + i]; }
    int base = blockIdx.x * 8;
    hs[ty][tx] = g_h[(base + ty) * EMB + tx];
    __syncthreads();
    float ap = b1[tx], aq = 0.f;
#pragma unroll
    for (int k = 0; k < EMB; k++) {
        float hv = hs[ty][k];
        ap = fmaf(hv, wd[k * EMB + tx], ap);
        aq = fmaf(hv, wsr[k * EMB + tx], aq);
    }
    g_p[(base + ty) * EMB + tx] = ap;
    g_q[(base + ty) * EMB + tx] = aq;
}

// ---------------- E1: y1 = p[dst]+q[src]+ea@Wc ; stats stage 0 -------------
__global__ void k_e1(const int* __restrict__ ei, const float* __restrict__ ea,
                     const float* __restrict__ wc, int layer) {
    __shared__ float s_sum[EMB], s_ss[EMB];
    int tid = threadIdx.x;
    if (tid < EMB) { s_sum[tid] = 0.f; s_ss[tid] = 0.f; }
    __syncthreads();
    int lane = tid & 31;
    int es = lane >> 3, cg = lane & 7, c0 = cg * 4;
    float4 w[8];
#pragma unroll
    for (int k = 0; k < 8; k++) w[k] = *(const float4*)(wc + k * EMB + c0);
    int nw = gridDim.x * (blockDim.x >> 5);
    int gw = blockIdx.x * (blockDim.x >> 5) + (tid >> 5);
    float4 sum = make_float4(0, 0, 0, 0), ss = make_float4(0, 0, 0, 0);
    for (int qd = gw; qd < Ee / 4; qd += nw) {
        int e = qd * 4 + es;
        int s = ei[e], d = ei[Ee + e];
        float4 pv = *(const float4*)(g_p + d * EMB + c0);
        float4 qv = *(const float4*)(g_q + s * EMB + c0);
        const float4* eap = (const float4*)(ea + e * ED);
        float4 e0 = eap[0], e1 = eap[1];
        float4 y = f4add(pv, qv);
        f4fma(y, e0.x, w[0]); f4fma(y, e0.y, w[1]); f4fma(y, e0.z, w[2]); f4fma(y, e0.w, w[3]);
        f4fma(y, e1.x, w[4]); f4fma(y, e1.y, w[5]); f4fma(y, e1.z, w[6]); f4fma(y, e1.w, w[7]);
        *(float4*)(g_y + (size_t)e * EMB + c0) = y;
        sum = f4add(sum, y);
        ss.x = fmaf(y.x, y.x, ss.x); ss.y = fmaf(y.y, y.y, ss.y);
        ss.z = fmaf(y.z, y.z, ss.z); ss.w = fmaf(y.w, y.w, ss.w);
    }
    stats_warp_to_shared(sum, ss, lane, c0, s_sum, s_ss);
    __syncthreads();
    if (tid < EMB) {
        atomicAdd(&g_stats[STAT_IDX(layer, 0, 0, tid)], s_sum[tid]);
        atomicAdd(&g_stats[STAT_IDX(layer, 0, 1, tid)], s_ss[tid]);
    }
}

// ---------------- E2: m1 = relu(bn(y1)) ; y2 = m1@W2+b2 ; stats stage 1 ----
__global__ void k_e2(const float* __restrict__ w2, const float* __restrict__ b2,
                     const float* __restrict__ g1, const float* __restrict__ be1, int layer) {
    __shared__ float s_w2[EMB * EMB];
    __shared__ float s_sum[EMB], s_ss[EMB];
    int tid = threadIdx.x;
    for (int i = tid; i < EMB * EMB; i += 256) s_w2[i] = w2[i];
    if (tid < EMB) { s_sum[tid] = 0.f; s_ss[tid] = 0.f; }
    __syncthreads();
    int lane = tid & 31;
    int es = lane >> 3, cg = lane & 7, c0 = cg * 4, base = lane & 24;
    float sc[4], sh[4];
    bn_coeffs(layer, 0, 1.f / Ee, g1, be1, c0, sc, sh);
    float4 bb = *(const float4*)(b2 + c0);
    const float4* w2v = (const float4*)s_w2;
    int nw = gridDim.x * (blockDim.x >> 5);
    int gw = blockIdx.x * (blockDim.x >> 5) + (tid >> 5);
    float4 sum = make_float4(0, 0, 0, 0), ssq = make_float4(0, 0, 0, 0);
    for (int qd = gw; qd < Ee / 4; qd += nw) {
        int e = qd * 4 + es;
        float4 y1 = *(const float4*)(g_y + (size_t)e * EMB + c0);
        float m[4];
        m[0] = fmaxf(fmaf(y1.x, sc[0], sh[0]), 0.f);
        m[1] = fmaxf(fmaf(y1.y, sc[1], sh[1]), 0.f);
        m[2] = fmaxf(fmaf(y1.z, sc[2], sh[2]), 0.f);
        m[3] = fmaxf(fmaf(y1.w, sc[3], sh[3]), 0.f);
        float4 acc = bb;
#pragma unroll
        for (int j = 0; j < EMB; j++) {
            float mj = __shfl_sync(0xffffffffu, m[j & 3], base + (j >> 2));
            f4fma(acc, mj, w2v[j * 8 + cg]);
        }
        *(float4*)(g_y + (size_t)e * EMB + c0) = acc;
        sum = f4add(sum, acc);
        ssq.x = fmaf(acc.x, acc.x, ssq.x); ssq.y = fmaf(acc.y, acc.y, ssq.y);
        ssq.z = fmaf(acc.z, acc.z, ssq.z); ssq.w = fmaf(acc.w, acc.w, ssq.w);
    }
    stats_warp_to_shared(sum, ssq, lane, c0, s_sum, s_ss);
    __syncthreads();
    if (tid < EMB) {
        atomicAdd(&g_stats[STAT_IDX(layer, 1, 0, tid)], s_sum[tid]);
        atomicAdd(&g_stats[STAT_IDX(layer, 1, 1, tid)], s_ss[tid]);
    }
}

// ---------------- E3: m2 = relu(bn(y2)) ; scatter-add to aggr[dst] ---------
__global__ void k_e3(const int* __restrict__ ei, const float* __restrict__ g2,
                     const float* __restrict__ be2, int layer) {
    int tid = threadIdx.x;
    int lane = tid & 31;
    int es = lane >> 3, cg = lane & 7, c0 = cg * 4;
    float sc[4], sh[4];
    bn_coeffs(layer, 1, 1.f / Ee, g2, be2, c0, sc, sh);
    int nw = gridDim.x * (blockDim.x >> 5);
    int gw = blockIdx.x * (blockDim.x >> 5) + (tid >> 5);
    for (int qd = gw; qd < Ee / 4; qd += nw) {
        int e = qd * 4 + es;
        int d = ei[Ee + e];
        float4 y = *(const float4*)(g_y + (size_t)e * EMB + c0);
        float m0 = fmaxf(fmaf(y.x, sc[0], sh[0]), 0.f);
        float m1 = fmaxf(fmaf(y.y, sc[1], sh[1]), 0.f);
        float m2 = fmaxf(fmaf(y.z, sc[2], sh[2]), 0.f);
        float m3 = fmaxf(fmaf(y.w, sc[3], sh[3]), 0.f);
        float* ap = g_aggr + d * EMB + c0;
        atomicAdd(ap + 0, m0); atomicAdd(ap + 1, m1);
        atomicAdd(ap + 2, m2); atomicAdd(ap + 3, m3);
    }
}

// ---------------- U1: y3 = [h||aggr]@Wu1 + b ; stats stage 2 ---------------
__global__ void k_u1(const float* __restrict__ w, const float* __restrict__ b, int layer) {
    __shared__ float sw[2 * EMB * EMB];
    __shared__ float s_sum[EMB], s_ss[EMB];
    int tid = threadIdx.x;
    for (int i = tid; i < 2 * EMB * EMB; i += 256) sw[i] = w[i];
    if (tid < EMB) { s_sum[tid] = 0.f; s_ss[tid] = 0.f; }
    __syncthreads();
    int lane = tid & 31;
    int es = lane >> 3, cg = lane & 7, c0 = cg * 4, base = lane & 24;
    float4 bb = *(const float4*)(b + c0);
    const float4* swv = (const float4*)sw;
    int nw = gridDim.x * (blockDim.x >> 5);
    int gw = blockIdx.x * (blockDim.x >> 5) + (tid >> 5);
    float4 sum = make_float4(0, 0, 0, 0), ssq = make_float4(0, 0, 0, 0);
    for (int qd = gw; qd < Nn / 4; qd += nw) {
        int n = qd * 4 + es;
        float4 h4 = *(const float4*)(g_h + n * EMB + c0);
        float4 a4 = *(const float4*)(g_aggr + n * EMB + c0);
        float hr[4] = {h4.x, h4.y, h4.z, h4.w};
        float ar[4] = {a4.x, a4.y, a4.z, a4.w};
        float4 acc = bb;
#pragma unroll
        for (int j = 0; j < EMB; j++) {
            float hj = __shfl_sync(0xffffffffu, hr[j & 3], base + (j >> 2));
            f4fma(acc, hj, swv[j * 8 + cg]);
        }
#pragma unroll
        for (int j = 0; j < EMB; j++) {
            float aj = __shfl_sync(0xffffffffu, ar[j & 3], base + (j >> 2));
            f4fma(acc, aj, swv[(EMB + j) * 8 + cg]);
        }
        *(float4*)(g_y3 + n * EMB + c0) = acc;
        sum = f4add(sum, acc);
        ssq.x = fmaf(acc.x, acc.x, ssq.x); ssq.y = fmaf(acc.y, acc.y, ssq.y);
        ssq.z = fmaf(acc.z, acc.z, ssq.z); ssq.w = fmaf(acc.w, acc.w, ssq.w);
    }
    stats_warp_to_shared(sum, ssq, lane, c0, s_sum, s_ss);
    __syncthreads();
    if (tid < EMB) {
        atomicAdd(&g_stats[STAT_IDX(layer, 2, 0, tid)], s_sum[tid]);
        atomicAdd(&g_stats[STAT_IDX(layer, 2, 1, tid)], s_ss[tid]);
    }
}

// ---------------- U2: r = relu(bn(y3)) ; y4 = r@Wu2+b ; stats stage 3 ------
__global__ void k_u2(const float* __restrict__ w2, const float* __restrict__ b2,
                     const float* __restrict__ g1, const float* __restrict__ be1, int layer) {
    __shared__ float s_w2[EMB * EMB];
    __shared__ float s_sum[EMB], s_ss[EMB];
    int tid = threadIdx.x;
    for (int i = tid; i < EMB * EMB; i += 256) s_w2[i] = w2[i];
    if (tid < EMB) { s_sum[tid] = 0.f; s_ss[tid] = 0.f; }
    __syncthreads();
    int lane = tid & 31;
    int es = lane >> 3, cg = lane & 7, c0 = cg * 4, base = lane & 24;
    float sc[4], sh[4];
    bn_coeffs(layer, 2, 1.f / Nn, g1, be1, c0, sc, sh);
    float4 bb = *(const float4*)(b2 + c0);
    const float4* w2v = (const float4*)s_w2;
    int nw = gridDim.x * (blockDim.x >> 5);
    int gw = blockIdx.x * (blockDim.x >> 5) + (tid >> 5);
    float4 sum = make_float4(0, 0, 0, 0), ssq = make_float4(0, 0, 0, 0);
    for (int qd = gw; qd < Nn / 4; qd += nw) {
        int n = qd * 4 + es;
        float4 y1 = *(const float4*)(g_y3 + n * EMB + c0);
        float m[4];
        m[0] = fmaxf(fmaf(y1.x, sc[0], sh[0]), 0.f);
        m[1] = fmaxf(fmaf(y1.y, sc[1], sh[1]), 0.f);
        m[2] = fmaxf(fmaf(y1.z, sc[2], sh[2]), 0.f);
        m[3] = fmaxf(fmaf(y1.w, sc[3], sh[3]), 0.f);
        float4 acc = bb;
#pragma unroll
        for (int j = 0; j < EMB; j++) {
            float mj = __shfl_sync(0xffffffffu, m[j & 3], base + (j >> 2));
            f4fma(acc, mj, w2v[j * 8 + cg]);
        }
        *(float4*)(g_y4 + n * EMB + c0) = acc;
        sum = f4add(sum, acc);
        ssq.x = fmaf(acc.x, acc.x, ssq.x); ssq.y = fmaf(acc.y, acc.y, ssq.y);
        ssq.z = fmaf(acc.z, acc.z, ssq.z); ssq.w = fmaf(acc.w, acc.w, ssq.w);
    }
    stats_warp_to_shared(sum, ssq, lane, c0, s_sum, s_ss);
    __syncthreads();
    if (tid < EMB) {
        atomicAdd(&g_stats[STAT_IDX(layer, 3, 0, tid)], s_sum[tid]);
        atomicAdd(&g_stats[STAT_IDX(layer, 3, 1, tid)], s_ss[tid]);
    }
}

// ---------------- U3: h += relu(bn(y4)) ------------------------------------
__global__ void k_u3(const float* __restrict__ g2, const float* __restrict__ be2, int layer) {
    int tid = threadIdx.x;
    int lane = tid & 31;
    int es = lane >> 3, cg = lane & 7, c0 = cg * 4;
    float sc[4], sh[4];
    bn_coeffs(layer, 3, 1.f / Nn, g2, be2, c0, sc, sh);
    int nw = gridDim.x * (blockDim.x >> 5);
    int gw = blockIdx.x * (blockDim.x >> 5) + (tid >> 5);
    for (int qd = gw; qd < Nn / 4; qd += nw) {
        int n = qd * 4 + es;
        float4 y = *(const float4*)(g_y4 + n * EMB + c0);
        float4 h = *(const float4*)(g_h + n * EMB + c0);
        h.x += fmaxf(fmaf(y.x, sc[0], sh[0]), 0.f);
        h.y += fmaxf(fmaf(y.y, sc[1], sh[1]), 0.f);
        h.z += fmaxf(fmaf(y.z, sc[2], sh[2]), 0.f);
        h.w += fmaxf(fmaf(y.w, sc[3], sh[3]), 0.f);
        *(float4*)(g_h + n * EMB + c0) = h;
    }
}

// ---------------- pooling + prediction -------------------------------------
__global__ void k_pool(const int* __restrict__ batch) {
    int idx = blockIdx.x * blockDim.x + threadIdx.x;
    if (idx >= Nn * 8) return;
    int n = idx >> 3, cg = idx & 7, c0 = cg * 4;
    int b = batch[n];
    float4 h = *(const float4*)(g_h + n * EMB + c0);
    float* pp = g_pool + b * EMB + c0;
    atomicAdd(pp + 0, h.x); atomicAdd(pp + 1, h.y);
    atomicAdd(pp + 2, h.z); atomicAdd(pp + 3, h.w);
    if (cg == 0) atomicAdd(&g_cnt[b], 1.0f);
}

__global__ void k_pred(const float* __restrict__ pw, const float* __restrict__ pb,
                       float* __restrict__ out) {
    int t = threadIdx.x;
    if (t >= NB * NOUT) return;
    int b = t / NOUT, o = t % NOUT;
    float inv = 1.f / fmaxf(g_cnt[b], 1.f);
    float s = 0.f;
#pragma unroll
    for (int j = 0; j < EMB; j++) s = fmaf(g_pool[b * EMB + j], pw[j * NOUT + o], s);
    out[t] = pb[o] + s * inv;
}

// ---------------- launch ----------------------------------------------------
extern "C" void kernel_launch(void* const* d_in, const int* in_sizes, int n_in,
                              void* d_out, int out_size) {
    const float *x, *edge_attr, *lin_in_w, *lin_in_b;
    const float *msg_w1, *msg_b1, *msg_g1, *msg_be1, *msg_w2, *msg_b2, *msg_g2, *msg_be2;
    const float *upd_w1, *upd_b1, *upd_g1, *upd_be1, *upd_w2, *upd_b2, *upd_g2, *upd_be2;
    const float *pred_w, *pred_b;
    const int *edge_idx, *batch;

    if (in_sizes[1] == 2 * Ee) {
        // setup_inputs() dict-insertion order:
        // x, edge_index, edge_attr, batch, lin_in_w, lin_in_b, msg_*, upd_*, pred_w, pred_b
        x        = (const float*)d_in[0];
        edge_idx = (const int*)  d_in[1];
        edge_attr= (const float*)d_in[2];
        batch    = (const int*)  d_in[3];
        lin_in_w = (const float*)d_in[4];
        lin_in_b = (const float*)d_in[5];
        msg_w1   = (const float*)d_in[6];
        msg_b1   = (const float*)d_in[7];
        msg_g1   = (const float*)d_in[8];
        msg_be1  = (const float*)d_in[9];
        msg_w2   = (const float*)d_in[10];
        msg_b2   = (const float*)d_in[11];
        msg_g2   = (const float*)d_in[12];
        msg_be2  = (const float*)d_in[13];
        upd_w1   = (const float*)d_in[14];
        upd_b1   = (const float*)d_in[15];
        upd_g1   = (const float*)d_in[16];
        upd_be1  = (const float*)d_in[17];
        upd_w2   = (const float*)d_in[18];
        upd_b2   = (const float*)d_in[19];
        upd_g2   = (const float*)d_in[20];
        upd_be2  = (const float*)d_in[21];
        pred_w   = (const float*)d_in[22];
        pred_b   = (const float*)d_in[23];
    } else {
        // reference() signature order (edge_index, batch at the end)
        x        = (const float*)d_in[0];
        edge_attr= (const float*)d_in[1];
        lin_in_w = (const float*)d_in[2];
        lin_in_b = (const float*)d_in[3];
        msg_w1   = (const float*)d_in[4];
        msg_b1   = (const float*)d_in[5];
        msg_g1   = (const float*)d_in[6];
        msg_be1  = (const float*)d_in[7];
        msg_w2   = (const float*)d_in[8];
        msg_b2   = (const float*)d_in[9];
        msg_g2   = (const float*)d_in[10];
        msg_be2  = (const float*)d_in[11];
        upd_w1   = (const float*)d_in[12];
        upd_b1   = (const float*)d_in[13];
        upd_g1   = (const float*)d_in[14];
        upd_be1  = (const float*)d_in[15];
        upd_w2   = (const float*)d_in[16];
        upd_b2   = (const float*)d_in[17];
        upd_g2   = (const float*)d_in[18];
        upd_be2  = (const float*)d_in[19];
        pred_w   = (const float*)d_in[20];
        pred_b   = (const float*)d_in[21];
        edge_idx = (const int*)  d_in[22];
        batch    = (const int*)  d_in[23];
    }
    float* out = (float*)d_out;

    k_zero_once<<<8, 256>>>();
    k_lin_in<<<Nn / 8, dim3(32, 8)>>>(x, lin_in_w, lin_in_b);
    for (int l = 0; l < NL; l++) {
        const float* w1 = msg_w1 + l * (2 * EMB + ED) * EMB;
        k_pq<<<Nn / 8, dim3(32, 8)>>>(w1, msg_b1 + l * EMB);
        k_e1<<<1184, 256>>>(edge_idx, edge_attr, w1 + 2 * EMB * EMB, l);
        k_e2<<<1184, 256>>>(msg_w2 + l * EMB * EMB, msg_b2 + l * EMB,
                            msg_g1 + l * EMB, msg_be1 + l * EMB, l);
        k_zero_aggr<<<(Nn * EMB / 4 + 255) / 256, 256>>>();
        k_e3<<<1184, 256>>>(edge_idx, msg_g2 + l * EMB, msg_be2 + l * EMB, l);
        k_u1<<<1184, 256>>>(upd_w1 + l * 2 * EMB * EMB, upd_b1 + l * EMB, l);
        k_u2<<<1184, 256>>>(upd_w2 + l * EMB * EMB, upd_b2 + l * EMB,
                            upd_g1 + l * EMB, upd_be1 + l * EMB, l);
        k_u3<<<1184, 256>>>(upd_g2 + l * EMB, upd_be2 + l * EMB, l);
    }
    k_pool<<<(Nn * 8 + 255) / 256, 256>>>(batch);
    k_pred<<<1, NB * NOUT>>>(pred_w, pred_b, out);
}

// round 3
// speedup vs baseline: 1.2071x; 1.2071x over previous
#include <cuda_runtime.h>
#include <cuda_fp16.h>

#define Nn    50000
#define Ee    800000
#define INDIM 128
#define EMB   32
#define ED    8
#define NL    4
#define NB    64
#define NOUT  10
#define EPS_BN 1e-5f
#define NBLK_SCAN 196   // ceil(Nn/256)

// ---------------- scratch (device globals) ----------------------------------
__device__ __align__(16) float  g_h[Nn * EMB];
__device__ __align__(16) float  g_p[Nn * EMB];
__device__ __align__(16) float  g_q[Nn * EMB];
__device__ __align__(16) float  g_y3[Nn * EMB];
__device__ __align__(16) float  g_y4[Nn * EMB];
__device__ __align__(16) __half g_yh[(size_t)Ee * EMB];   // 51.2 MB fp16 edge scratch
__device__ __align__(16) float  g_stats[NL * 4 * 2 * EMB];
__device__ __align__(16) float  g_pool[NB * EMB];
__device__ __align__(16) float  g_cnt[NB];
// CSR for dst aggregation (built once per launch)
__device__ int g_deg[Nn];
__device__ int g_rowstart[Nn + 1];
__device__ int g_cursor[Nn];
__device__ int g_elist[Ee];
__device__ int g_bsum[NBLK_SCAN];
__device__ int g_boff[NBLK_SCAN];

#define STAT_IDX(l, stage, which, c) ((((l) * 4 + (stage)) * 2 + (which)) * EMB + (c))

// ---------------- helpers ---------------------------------------------------
__device__ __forceinline__ float4 f4add(float4 a, float4 b) {
    return make_float4(a.x + b.x, a.y + b.y, a.z + b.z, a.w + b.w);
}
__device__ __forceinline__ void f4fma(float4& a, float s, float4 w) {
    a.x = fmaf(s, w.x, a.x); a.y = fmaf(s, w.y, a.y);
    a.z = fmaf(s, w.z, a.z); a.w = fmaf(s, w.w, a.w);
}
__device__ __forceinline__ void store_h4(__half* p, float4 v) {
    union { __half2 h[2]; uint2 u; } cv;
    cv.h[0] = __float22half2_rn(make_float2(v.x, v.y));
    cv.h[1] = __float22half2_rn(make_float2(v.z, v.w));
    *(uint2*)p = cv.u;
}
__device__ __forceinline__ float4 load_h4(const __half* p) {
    union { uint2 u; __half2 h[2]; } cv;
    cv.u = *(const uint2*)p;
    float2 a = __half22float2(cv.h[0]);
    float2 b = __half22float2(cv.h[1]);
    return make_float4(a.x, a.y, b.x, b.y);
}

__device__ __forceinline__ void stats_warp_to_shared(float4 sum, float4 ss, int lane,
                                                     int c0, float* s_sum, float* s_ss) {
#pragma unroll
    for (int off = 8; off < 32; off <<= 1) {
        sum.x += __shfl_xor_sync(0xffffffffu, sum.x, off);
        sum.y += __shfl_xor_sync(0xffffffffu, sum.y, off);
        sum.z += __shfl_xor_sync(0xffffffffu, sum.z, off);
        sum.w += __shfl_xor_sync(0xffffffffu, sum.w, off);
        ss.x  += __shfl_xor_sync(0xffffffffu, ss.x, off);
        ss.y  += __shfl_xor_sync(0xffffffffu, ss.y, off);
        ss.z  += __shfl_xor_sync(0xffffffffu, ss.z, off);
        ss.w  += __shfl_xor_sync(0xffffffffu, ss.w, off);
    }
    if (lane < 8) {
        atomicAdd(&s_sum[c0 + 0], sum.x); atomicAdd(&s_sum[c0 + 1], sum.y);
        atomicAdd(&s_sum[c0 + 2], sum.z); atomicAdd(&s_sum[c0 + 3], sum.w);
        atomicAdd(&s_ss[c0 + 0], ss.x);   atomicAdd(&s_ss[c0 + 1], ss.y);
        atomicAdd(&s_ss[c0 + 2], ss.z);   atomicAdd(&s_ss[c0 + 3], ss.w);
    }
}

__device__ __forceinline__ void bn_coeffs(int l, int stage, float inv_n,
                                          const float* __restrict__ gamma,
                                          const float* __restrict__ beta,
                                          int c0, float sc[4], float sh[4]) {
#pragma unroll
    for (int i = 0; i < 4; i++) {
        int c = c0 + i;
        float s1 = g_stats[STAT_IDX(l, stage, 0, c)];
        float s2 = g_stats[STAT_IDX(l, stage, 1, c)];
        float mu = s1 * inv_n;
        float var = s2 * inv_n - mu * mu;
        float rs = rsqrtf(var + EPS_BN);
        sc[i] = rs * gamma[c];
        sh[i] = beta[c] - mu * sc[i];
    }
}

// ---------------- init + CSR build ------------------------------------------
__global__ void k_zero_once() {
    int i = blockIdx.x * blockDim.x + threadIdx.x;
    if (i < NL * 4 * 2 * EMB) g_stats[i] = 0.f;
    if (i < NB * EMB) g_pool[i] = 0.f;
    if (i < NB) g_cnt[i] = 0.f;
    if (i < Nn) g_deg[i] = 0;
}
__global__ void k_hist(const int* __restrict__ ei) {
    int i = blockIdx.x * blockDim.x + threadIdx.x;
    if (i < Ee) atomicAdd(&g_deg[ei[Ee + i]], 1);
}
__global__ void k_scan1() {
    __shared__ int s[256];
    int t = threadIdx.x;
    int i = blockIdx.x * 256 + t;
    int v = (i < Nn) ? g_deg[i] : 0;
    s[t] = v;
    __syncthreads();
#pragma unroll
    for (int off = 1; off < 256; off <<= 1) {
        int add = (t >= off) ? s[t - off] : 0;
        __syncthreads();
        s[t] += add;
        __syncthreads();
    }
    if (i < Nn) g_rowstart[i + 1] = s[t];
    if (t == 255) g_bsum[blockIdx.x] = s[255];
}
__global__ void k_scan2() {
    __shared__ int s[256];
    int t = threadIdx.x;
    int v = (t < NBLK_SCAN) ? g_bsum[t] : 0;
    s[t] = v;
    __syncthreads();
#pragma unroll
    for (int off = 1; off < 256; off <<= 1) {
        int add = (t >= off) ? s[t - off] : 0;
        __syncthreads();
        s[t] += add;
        __syncthreads();
    }
    if (t < NBLK_SCAN) g_boff[t] = s[t] - v;   // exclusive
}
__global__ void k_scan3() {
    int i = blockIdx.x * blockDim.x + threadIdx.x;
    if (i < Nn) g_rowstart[i + 1] += g_boff[i >> 8];
    if (i == 0) g_rowstart[0] = 0;
}
__global__ void k_cursor() {
    int i = blockIdx.x * blockDim.x + threadIdx.x;
    if (i < Nn) g_cursor[i] = g_rowstart[i];
}
__global__ void k_fill(const int* __restrict__ ei) {
    int i = blockIdx.x * blockDim.x + threadIdx.x;
    if (i < Ee) {
        int d = ei[Ee + i];
        int pos = atomicAdd(&g_cursor[d], 1);
        g_elist[pos] = i;
    }
}

// ---------------- lin_in: h = x @ W + b -------------------------------------
__global__ void k_lin_in(const float* __restrict__ x, const float* __restrict__ w,
                         const float* __restrict__ b) {
    __shared__ float ws[INDIM * EMB];
    __shared__ float xs[8][INDIM];
    int tx = threadIdx.x, ty = threadIdx.y;
    int tid = ty * 32 + tx;
    for (int i = tid; i < INDIM * EMB; i += 256) ws[i] = w[i];
    int base = blockIdx.x * 8;
    for (int i = tid; i < 8 * INDIM; i += 256) {
        int nloc = i >> 7, k = i & 127;
        xs[nloc][k] = x[(base + nloc) * INDIM + k];
    }
    __syncthreads();
    float acc = b[tx];
#pragma unroll 8
    for (int k = 0; k < INDIM; k++) acc = fmaf(xs[ty][k], ws[k * EMB + tx], acc);
    g_h[(base + ty) * EMB + tx] = acc;
}

// ---------------- per-layer node projections p, q ---------------------------
__global__ void k_pq(const float* __restrict__ w1, const float* __restrict__ b1) {
    __shared__ float wd[EMB * EMB];
    __shared__ float wsr[EMB * EMB];
    __shared__ float hs[8][EMB];
    int tx = threadIdx.x, ty = threadIdx.y;
    int tid = ty * 32 + tx;
    for (int i = tid; i < EMB * EMB; i += 256) { wd[i] = w1[i]; wsr[i] = w1[EMB * EMB + i]; }
    int base = blockIdx.x * 8;
    hs[ty][tx] = g_h[(base + ty) * EMB + tx];
    __syncthreads();
    float ap = b1[tx], aq = 0.f;
#pragma unroll
    for (int k = 0; k < EMB; k++) {
        float hv = hs[ty][k];
        ap = fmaf(hv, wd[k * EMB + tx], ap);
        aq = fmaf(hv, wsr[k * EMB + tx], aq);
    }
    g_p[(base + ty) * EMB + tx] = ap;
    g_q[(base + ty) * EMB + tx] = aq;
}

// ---------------- E1: y1 = p[dst]+q[src]+ea@Wc ; stats stage 0 --------------
__global__ void k_e1(const int* __restrict__ ei, const float* __restrict__ ea,
                     const float* __restrict__ wc, int layer) {
    __shared__ float s_sum[EMB], s_ss[EMB];
    int tid = threadIdx.x;
    if (tid < EMB) { s_sum[tid] = 0.f; s_ss[tid] = 0.f; }
    __syncthreads();
    int lane = tid & 31;
    int es = lane >> 3, cg = lane & 7, c0 = cg * 4;
    float4 w[8];
#pragma unroll
    for (int k = 0; k < 8; k++) w[k] = *(const float4*)(wc + k * EMB + c0);
    int nw = gridDim.x * (blockDim.x >> 5);
    int gw = blockIdx.x * (blockDim.x >> 5) + (tid >> 5);
    float4 sum = make_float4(0, 0, 0, 0), ss = make_float4(0, 0, 0, 0);
    for (int qd = gw; qd < Ee / 4; qd += nw) {
        int e = qd * 4 + es;
        int s = ei[e], d = ei[Ee + e];
        float4 pv = *(const float4*)(g_p + d * EMB + c0);
        float4 qv = *(const float4*)(g_q + s * EMB + c0);
        const float4* eap = (const float4*)(ea + e * ED);
        float4 e0 = eap[0], e1 = eap[1];
        float4 y = f4add(pv, qv);
        f4fma(y, e0.x, w[0]); f4fma(y, e0.y, w[1]); f4fma(y, e0.z, w[2]); f4fma(y, e0.w, w[3]);
        f4fma(y, e1.x, w[4]); f4fma(y, e1.y, w[5]); f4fma(y, e1.z, w[6]); f4fma(y, e1.w, w[7]);
        store_h4(g_yh + (size_t)e * EMB + c0, y);
        sum = f4add(sum, y);
        ss.x = fmaf(y.x, y.x, ss.x); ss.y = fmaf(y.y, y.y, ss.y);
        ss.z = fmaf(y.z, y.z, ss.z); ss.w = fmaf(y.w, y.w, ss.w);
    }
    stats_warp_to_shared(sum, ss, lane, c0, s_sum, s_ss);
    __syncthreads();
    if (tid < EMB) {
        atomicAdd(&g_stats[STAT_IDX(layer, 0, 0, tid)], s_sum[tid]);
        atomicAdd(&g_stats[STAT_IDX(layer, 0, 1, tid)], s_ss[tid]);
    }
}

// ---------------- E2: m1 = relu(bn(y1)) ; y2 = m1@W2+b2 ; stats stage 1 -----
__global__ void k_e2(const float* __restrict__ w2, const float* __restrict__ b2,
                     const float* __restrict__ g1, const float* __restrict__ be1, int layer) {
    __shared__ float s_w2[EMB * EMB];
    __shared__ float s_sum[EMB], s_ss[EMB];
    int tid = threadIdx.x;
    for (int i = tid; i < EMB * EMB; i += 256) s_w2[i] = w2[i];
    if (tid < EMB) { s_sum[tid] = 0.f; s_ss[tid] = 0.f; }
    __syncthreads();
    int lane = tid & 31;
    int es = lane >> 3, cg = lane & 7, c0 = cg * 4, base = lane & 24;
    float sc[4], sh[4];
    bn_coeffs(layer, 0, 1.f / Ee, g1, be1, c0, sc, sh);
    float4 bb = *(const float4*)(b2 + c0);
    const float4* w2v = (const float4*)s_w2;
    int nw = gridDim.x * (blockDim.x >> 5);
    int gw = blockIdx.x * (blockDim.x >> 5) + (tid >> 5);
    float4 sum = make_float4(0, 0, 0, 0), ssq = make_float4(0, 0, 0, 0);
    for (int qd = gw; qd < Ee / 4; qd += nw) {
        int e = qd * 4 + es;
        float4 y1 = load_h4(g_yh + (size_t)e * EMB + c0);
        float m[4];
        m[0] = fmaxf(fmaf(y1.x, sc[0], sh[0]), 0.f);
        m[1] = fmaxf(fmaf(y1.y, sc[1], sh[1]), 0.f);
        m[2] = fmaxf(fmaf(y1.z, sc[2], sh[2]), 0.f);
        m[3] = fmaxf(fmaf(y1.w, sc[3], sh[3]), 0.f);
        float4 acc = bb;
#pragma unroll
        for (int j = 0; j < EMB; j++) {
            float mj = __shfl_sync(0xffffffffu, m[j & 3], base + (j >> 2));
            f4fma(acc, mj, w2v[j * 8 + cg]);
        }
        store_h4(g_yh + (size_t)e * EMB + c0, acc);
        sum = f4add(sum, acc);
        ssq.x = fmaf(acc.x, acc.x, ssq.x); ssq.y = fmaf(acc.y, acc.y, ssq.y);
        ssq.z = fmaf(acc.z, acc.z, ssq.z); ssq.w = fmaf(acc.w, acc.w, ssq.w);
    }
    stats_warp_to_shared(sum, ssq, lane, c0, s_sum, s_ss);
    __syncthreads();
    if (tid < EMB) {
        atomicAdd(&g_stats[STAT_IDX(layer, 1, 0, tid)], s_sum[tid]);
        atomicAdd(&g_stats[STAT_IDX(layer, 1, 1, tid)], s_ss[tid]);
    }
}

// ---- fused E3+U1: aggr[n] = sum_{e in CSR(n)} relu(bn(y2[e])) ;
//      y3 = [h||aggr]@Wu1 + b ; stats stage 2 -------------------------------
__global__ void k_e3u1(const float* __restrict__ w, const float* __restrict__ b,
                       const float* __restrict__ g2, const float* __restrict__ be2,
                       int layer) {
    __shared__ float sw[2 * EMB * EMB];
    __shared__ float s_sum[EMB], s_ss[EMB];
    int tid = threadIdx.x;
    for (int i = tid; i < 2 * EMB * EMB; i += 256) sw[i] = w[i];
    if (tid < EMB) { s_sum[tid] = 0.f; s_ss[tid] = 0.f; }
    __syncthreads();
    int lane = tid & 31;
    int es = lane >> 3, cg = lane & 7, c0 = cg * 4, base = lane & 24;
    float4 sum = make_float4(0, 0, 0, 0), ssq = make_float4(0, 0, 0, 0);

    int quad = blockIdx.x * 8 + (tid >> 5);
    if (quad * 4 < Nn) {
        float sc[4], sh[4];
        bn_coeffs(layer, 1, 1.f / Ee, g2, be2, c0, sc, sh);
        int n = quad * 4 + es;
        int rs = g_rowstart[n], re = g_rowstart[n + 1];
        float4 ag = make_float4(0, 0, 0, 0);
        for (int i = rs; i < re; i++) {
            int e = g_elist[i];
            float4 y = load_h4(g_yh + (size_t)e * EMB + c0);
            ag.x += fmaxf(fmaf(y.x, sc[0], sh[0]), 0.f);
            ag.y += fmaxf(fmaf(y.y, sc[1], sh[1]), 0.f);
            ag.z += fmaxf(fmaf(y.z, sc[2], sh[2]), 0.f);
            ag.w += fmaxf(fmaf(y.w, sc[3], sh[3]), 0.f);
        }
        float4 h4 = *(const float4*)(g_h + n * EMB + c0);
        float hr[4] = {h4.x, h4.y, h4.z, h4.w};
        float ar[4] = {ag.x, ag.y, ag.z, ag.w};
        const float4* swv = (const float4*)sw;
        float4 acc = *(const float4*)(b + c0);
#pragma unroll
        for (int j = 0; j < EMB; j++) {
            float hj = __shfl_sync(0xffffffffu, hr[j & 3], base + (j >> 2));
            f4fma(acc, hj, swv[j * 8 + cg]);
        }
#pragma unroll
        for (int j = 0; j < EMB; j++) {
            float aj = __shfl_sync(0xffffffffu, ar[j & 3], base + (j >> 2));
            f4fma(acc, aj, swv[(EMB + j) * 8 + cg]);
        }
        *(float4*)(g_y3 + n * EMB + c0) = acc;
        sum = acc;
        ssq.x = acc.x * acc.x; ssq.y = acc.y * acc.y;
        ssq.z = acc.z * acc.z; ssq.w = acc.w * acc.w;
    }
    stats_warp_to_shared(sum, ssq, lane, c0, s_sum, s_ss);
    __syncthreads();
    if (tid < EMB) {
        atomicAdd(&g_stats[STAT_IDX(layer, 2, 0, tid)], s_sum[tid]);
        atomicAdd(&g_stats[STAT_IDX(layer, 2, 1, tid)], s_ss[tid]);
    }
}

// ---------------- U2: r = relu(bn(y3)) ; y4 = r@Wu2+b ; stats stage 3 -------
__global__ void k_u2(const float* __restrict__ w2, const float* __restrict__ b2,
                     const float* __restrict__ g1, const float* __restrict__ be1, int layer) {
    __shared__ float s_w2[EMB * EMB];
    __shared__ float s_sum[EMB], s_ss[EMB];
    int tid = threadIdx.x;
    for (int i = tid; i < EMB * EMB; i += 256) s_w2[i] = w2[i];
    if (tid < EMB) { s_sum[tid] = 0.f; s_ss[tid] = 0.f; }
    __syncthreads();
    int lane = tid & 31;
    int es = lane >> 3, cg = lane & 7, c0 = cg * 4, base = lane & 24;
    float sc[4], sh[4];
    bn_coeffs(layer, 2, 1.f / Nn, g1, be1, c0, sc, sh);
    float4 bb = *(const float4*)(b2 + c0);
    const float4* w2v = (const float4*)s_w2;
    int nw = gridDim.x * (blockDim.x >> 5);
    int gw = blockIdx.x * (blockDim.x >> 5) + (tid >> 5);
    float4 sum = make_float4(0, 0, 0, 0), ssq = make_float4(0, 0, 0, 0);
    for (int qd = gw; qd < Nn / 4; qd += nw) {
        int n = qd * 4 + es;
        float4 y1 = *(const float4*)(g_y3 + n * EMB + c0);
        float m[4];
        m[0] = fmaxf(fmaf(y1.x, sc[0], sh[0]), 0.f);
        m[1] = fmaxf(fmaf(y1.y, sc[1], sh[1]), 0.f);
        m[2] = fmaxf(fmaf(y1.z, sc[2], sh[2]), 0.f);
        m[3] = fmaxf(fmaf(y1.w, sc[3], sh[3]), 0.f);
        float4 acc = bb;
#pragma unroll
        for (int j = 0; j < EMB; j++) {
            float mj = __shfl_sync(0xffffffffu, m[j & 3], base + (j >> 2));
            f4fma(acc, mj, w2v[j * 8 + cg]);
        }
        *(float4*)(g_y4 + n * EMB + c0) = acc;
        sum = f4add(sum, acc);
        ssq.x = fmaf(acc.x, acc.x, ssq.x); ssq.y = fmaf(acc.y, acc.y, ssq.y);
        ssq.z = fmaf(acc.z, acc.z, ssq.z); ssq.w = fmaf(acc.w, acc.w, ssq.w);
    }
    stats_warp_to_shared(sum, ssq, lane, c0, s_sum, s_ss);
    __syncthreads();
    if (tid < EMB) {
        atomicAdd(&g_stats[STAT_IDX(layer, 3, 0, tid)], s_sum[tid]);
        atomicAdd(&g_stats[STAT_IDX(layer, 3, 1, tid)], s_ss[tid]);
    }
}

// ---------------- U3: h += relu(bn(y4)) -------------------------------------
__global__ void k_u3(const float* __restrict__ g2, const float* __restrict__ be2, int layer) {
    int tid = threadIdx.x;
    int lane = tid & 31;
    int es = lane >> 3, cg = lane & 7, c0 = cg * 4;
    float sc[4], sh[4];
    bn_coeffs(layer, 3, 1.f / Nn, g2, be2, c0, sc, sh);
    int nw = gridDim.x * (blockDim.x >> 5);
    int gw = blockIdx.x * (blockDim.x >> 5) + (tid >> 5);
    for (int qd = gw; qd < Nn / 4; qd += nw) {
        int n = qd * 4 + es;
        float4 y = *(const float4*)(g_y4 + n * EMB + c0);
        float4 h = *(const float4*)(g_h + n * EMB + c0);
        h.x += fmaxf(fmaf(y.x, sc[0], sh[0]), 0.f);
        h.y += fmaxf(fmaf(y.y, sc[1], sh[1]), 0.f);
        h.z += fmaxf(fmaf(y.z, sc[2], sh[2]), 0.f);
        h.w += fmaxf(fmaf(y.w, sc[3], sh[3]), 0.f);
        *(float4*)(g_h + n * EMB + c0) = h;
    }
}

// ---------------- pooling + prediction --------------------------------------
__global__ void k_pool(const int* __restrict__ batch) {
    int idx = blockIdx.x * blockDim.x + threadIdx.x;
    if (idx >= Nn * 8) return;
    int n = idx >> 3, cg = idx & 7, c0 = cg * 4;
    int b = batch[n];
    float4 h = *(const float4*)(g_h + n * EMB + c0);
    float* pp = g_pool + b * EMB + c0;
    atomicAdd(pp + 0, h.x); atomicAdd(pp + 1, h.y);
    atomicAdd(pp + 2, h.z); atomicAdd(pp + 3, h.w);
    if (cg == 0) atomicAdd(&g_cnt[b], 1.0f);
}

__global__ void k_pred(const float* __restrict__ pw, const float* __restrict__ pb,
                       float* __restrict__ out) {
    int t = threadIdx.x;
    if (t >= NB * NOUT) return;
    int b = t / NOUT, o = t % NOUT;
    float inv = 1.f / fmaxf(g_cnt[b], 1.f);
    float s = 0.f;
#pragma unroll
    for (int j = 0; j < EMB; j++) s = fmaf(g_pool[b * EMB + j], pw[j * NOUT + o], s);
    out[t] = pb[o] + s * inv;
}

// ---------------- launch -----------------------------------------------------
extern "C" void kernel_launch(void* const* d_in, const int* in_sizes, int n_in,
                              void* d_out, int out_size) {
    const float *x, *edge_attr, *lin_in_w, *lin_in_b;
    const float *msg_w1, *msg_b1, *msg_g1, *msg_be1, *msg_w2, *msg_b2, *msg_g2, *msg_be2;
    const float *upd_w1, *upd_b1, *upd_g1, *upd_be1, *upd_w2, *upd_b2, *upd_g2, *upd_be2;
    const float *pred_w, *pred_b;
    const int *edge_idx, *batch;

    if (in_sizes[1] == 2 * Ee) {
        x        = (const float*)d_in[0];
        edge_idx = (const int*)  d_in[1];
        edge_attr= (const float*)d_in[2];
        batch    = (const int*)  d_in[3];
        lin_in_w = (const float*)d_in[4];
        lin_in_b = (const float*)d_in[5];
        msg_w1   = (const float*)d_in[6];
        msg_b1   = (const float*)d_in[7];
        msg_g1   = (const float*)d_in[8];
        msg_be1  = (const float*)d_in[9];
        msg_w2   = (const float*)d_in[10];
        msg_b2   = (const float*)d_in[11];
        msg_g2   = (const float*)d_in[12];
        msg_be2  = (const float*)d_in[13];
        upd_w1   = (const float*)d_in[14];
        upd_b1   = (const float*)d_in[15];
        upd_g1   = (const float*)d_in[16];
        upd_be1  = (const float*)d_in[17];
        upd_w2   = (const float*)d_in[18];
        upd_b2   = (const float*)d_in[19];
        upd_g2   = (const float*)d_in[20];
        upd_be2  = (const float*)d_in[21];
        pred_w   = (const float*)d_in[22];
        pred_b   = (const float*)d_in[23];
    } else {
        x        = (const float*)d_in[0];
        edge_attr= (const float*)d_in[1];
        lin_in_w = (const float*)d_in[2];
        lin_in_b = (const float*)d_in[3];
        msg_w1   = (const float*)d_in[4];
        msg_b1   = (const float*)d_in[5];
        msg_g1   = (const float*)d_in[6];
        msg_be1  = (const float*)d_in[7];
        msg_w2   = (const float*)d_in[8];
        msg_b2   = (const float*)d_in[9];
        msg_g2   = (const float*)d_in[10];
        msg_be2  = (const float*)d_in[11];
        upd_w1   = (const float*)d_in[12];
        upd_b1   = (const float*)d_in[13];
        upd_g1   = (const float*)d_in[14];
        upd_be1  = (const float*)d_in[15];
        upd_w2   = (const float*)d_in[16];
        upd_b2   = (const float*)d_in[17];
        upd_g2   = (const float*)d_in[18];
        upd_be2  = (const float*)d_in[19];
        pred_w   = (const float*)d_in[20];
        pred_b   = (const float*)d_in[21];
        edge_idx = (const int*)  d_in[22];
        batch    = (const int*)  d_in[23];
    }
    float* out = (float*)d_out;

    // init + CSR build (dst is launch-invariant within one call)
    k_zero_once<<<NBLK_SCAN, 256>>>();
    k_hist<<<(Ee + 255) / 256, 256>>>(edge_idx);
    k_scan1<<<NBLK_SCAN, 256>>>();
    k_scan2<<<1, 256>>>();
    k_scan3<<<NBLK_SCAN, 256>>>();
    k_cursor<<<NBLK_SCAN, 256>>>();
    k_fill<<<(Ee + 255) / 256, 256>>>(edge_idx);

    k_lin_in<<<Nn / 8, dim3(32, 8)>>>(x, lin_in_w, lin_in_b);
    for (int l = 0; l < NL; l++) {
        const float* w1 = msg_w1 + l * (2 * EMB + ED) * EMB;
        k_pq<<<Nn / 8, dim3(32, 8)>>>(w1, msg_b1 + l * EMB);
        k_e1<<<1184, 256>>>(edge_idx, edge_attr, w1 + 2 * EMB * EMB, l);
        k_e2<<<1184, 256>>>(msg_w2 + l * EMB * EMB, msg_b2 + l * EMB,
                            msg_g1 + l * EMB, msg_be1 + l * EMB, l);
        k_e3u1<<<(Nn / 4 + 7) / 8, 256>>>(upd_w1 + l * 2 * EMB * EMB, upd_b1 + l * EMB,
                                          msg_g2 + l * EMB, msg_be2 + l * EMB, l);
        k_u2<<<1184, 256>>>(upd_w2 + l * EMB * EMB, upd_b2 + l * EMB,
                            upd_g1 + l * EMB, upd_be1 + l * EMB, l);
        k_u3<<<1184, 256>>>(upd_g2 + l * EMB, upd_be2 + l * EMB, l);
    }
    k_pool<<<(Nn * 8 + 255) / 256, 256>>>(batch);
    k_pred<<<1, NB * NOUT>>>(pred_w, pred_b, out);
}